// round 1
// baseline (speedup 1.0000x reference)
#include <cuda_runtime.h>

#define HID 128
#define MAXN 50000
#define MAXE 640000

// ---- scratch (device globals: no allocation allowed) ----
__device__ __align__(16) float g_P[(size_t)MAXN * 2 * HID];   // [:,0:128]=z@W1, [:,128:256]=z@W2+b_msg
__device__ __align__(16) float g_agg[(size_t)MAXN * HID];
__device__ int   g_count[MAXN];
__device__ int   g_off[MAXN + 1];
__device__ int   g_cur[MAXN];
__device__ int   g_srcs[MAXE];
__device__ __align__(16) float g_ws[MAXE];

#define BM 128
#define BN 128
#define BK 16
#define TM 8
#define TN 8

// ============================================================
// Projection GEMM: g_P[M,256] = z[M,128] @ [W1 | W2] (+ b_msg on right half)
// blockIdx.y = half (0: W_msg rows 0..127, 1: rows 128..255)
// ============================================================
__global__ void __launch_bounds__(256, 2) sgemm_proj(
    const float* __restrict__ z, const float* __restrict__ Wm,
    const float* __restrict__ bm, int M)
{
    __shared__ __align__(16) float As[BK][BM];
    __shared__ __align__(16) float Bs[BK][BN];

    const int m0   = blockIdx.x * BM;
    const int half = blockIdx.y;
    const float* B = Wm + (size_t)half * 128 * HID;  // [128,128], ld=128

    const int t  = threadIdx.x;
    const int tx = t & 15;
    const int ty = t >> 4;

    const int a_row = t >> 2;
    const int a_col = (t & 3) * 4;
    const int b_row = t >> 5;
    const int b_col = (t & 31) * 4;

    float acc[TM][TN];
#pragma unroll
    for (int i = 0; i < TM; i++)
#pragma unroll
        for (int j = 0; j < TN; j++) acc[i][j] = 0.0f;

    for (int k0 = 0; k0 < HID; k0 += BK) {
#pragma unroll
        for (int r = 0; r < 2; r++) {
            int m = m0 + a_row + r * 64;
            float4 v = make_float4(0.f, 0.f, 0.f, 0.f);
            if (m < M) v = *(const float4*)(z + (size_t)m * HID + k0 + a_col);
            As[a_col + 0][a_row + r * 64] = v.x;
            As[a_col + 1][a_row + r * 64] = v.y;
            As[a_col + 2][a_row + r * 64] = v.z;
            As[a_col + 3][a_row + r * 64] = v.w;
        }
#pragma unroll
        for (int r = 0; r < 2; r++) {
            int k = k0 + b_row + r * 8;
            *(float4*)(&Bs[b_row + r * 8][b_col]) =
                *(const float4*)(B + (size_t)k * HID + b_col);
        }
        __syncthreads();

#pragma unroll
        for (int k = 0; k < BK; k++) {
            float ar[TM], br[TN];
            *(float4*)&ar[0] = *(const float4*)&As[k][ty * TM];
            *(float4*)&ar[4] = *(const float4*)&As[k][ty * TM + 4];
            *(float4*)&br[0] = *(const float4*)&Bs[k][tx * TN];
            *(float4*)&br[4] = *(const float4*)&Bs[k][tx * TN + 4];
#pragma unroll
            for (int i = 0; i < TM; i++)
#pragma unroll
                for (int j = 0; j < TN; j++)
                    acc[i][j] = fmaf(ar[i], br[j], acc[i][j]);
        }
        __syncthreads();
    }

#pragma unroll
    for (int i = 0; i < TM; i++) {
        int m = m0 + ty * TM + i;
        if (m >= M) continue;
#pragma unroll
        for (int j = 0; j < TN; j++) {
            int col = tx * TN + j;
            float v = acc[i][j];
            if (half) v += bm[col];
            g_P[(size_t)m * (2 * HID) + half * HID + col] = v;
        }
    }
}

// ============================================================
// Update GEMM: out[M,128] = [z | agg][M,256] @ W_upd[256,128] + b_upd
// ============================================================
__global__ void __launch_bounds__(256, 2) sgemm_upd(
    const float* __restrict__ z, const float* __restrict__ Wu,
    const float* __restrict__ bu, float* __restrict__ out, int M)
{
    __shared__ __align__(16) float As[BK][BM];
    __shared__ __align__(16) float Bs[BK][BN];

    const int m0 = blockIdx.x * BM;
    const int t  = threadIdx.x;
    const int tx = t & 15;
    const int ty = t >> 4;

    const int a_row = t >> 2;
    const int a_col = (t & 3) * 4;
    const int b_row = t >> 5;
    const int b_col = (t & 31) * 4;

    float acc[TM][TN];
#pragma unroll
    for (int i = 0; i < TM; i++)
#pragma unroll
        for (int j = 0; j < TN; j++) acc[i][j] = 0.0f;

    for (int k0 = 0; k0 < 2 * HID; k0 += BK) {
        // Whole BK-slab comes from one source (k0 multiple of 16, HID=128)
        const float* Asrc = (k0 < HID) ? z : g_agg;
        int kbase = (k0 < HID) ? k0 : (k0 - HID);
#pragma unroll
        for (int r = 0; r < 2; r++) {
            int m = m0 + a_row + r * 64;
            float4 v = make_float4(0.f, 0.f, 0.f, 0.f);
            if (m < M) v = *(const float4*)(Asrc + (size_t)m * HID + kbase + a_col);
            As[a_col + 0][a_row + r * 64] = v.x;
            As[a_col + 1][a_row + r * 64] = v.y;
            As[a_col + 2][a_row + r * 64] = v.z;
            As[a_col + 3][a_row + r * 64] = v.w;
        }
#pragma unroll
        for (int r = 0; r < 2; r++) {
            int k = k0 + b_row + r * 8;
            *(float4*)(&Bs[b_row + r * 8][b_col]) =
                *(const float4*)(Wu + (size_t)k * HID + b_col);
        }
        __syncthreads();

#pragma unroll
        for (int k = 0; k < BK; k++) {
            float ar[TM], br[TN];
            *(float4*)&ar[0] = *(const float4*)&As[k][ty * TM];
            *(float4*)&ar[4] = *(const float4*)&As[k][ty * TM + 4];
            *(float4*)&br[0] = *(const float4*)&Bs[k][tx * TN];
            *(float4*)&br[4] = *(const float4*)&Bs[k][tx * TN + 4];
#pragma unroll
            for (int i = 0; i < TM; i++)
#pragma unroll
                for (int j = 0; j < TN; j++)
                    acc[i][j] = fmaf(ar[i], br[j], acc[i][j]);
        }
        __syncthreads();
    }

#pragma unroll
    for (int i = 0; i < TM; i++) {
        int m = m0 + ty * TM + i;
        if (m >= M) continue;
#pragma unroll
        for (int j = 0; j < TN; j++) {
            int col = tx * TN + j;
            out[(size_t)m * HID + col] = acc[i][j] + bu[col];
        }
    }
}

// ============================================================
// CSR build: zero -> histogram -> scan -> scatter
// ============================================================
__global__ void zero_counts(int n) {
    int i = blockIdx.x * blockDim.x + threadIdx.x;
    if (i < n) g_count[i] = 0;
}

__global__ void hist_kernel(const int* __restrict__ dists, int E) {
    int e = blockIdx.x * blockDim.x + threadIdx.x;
    if (e < E) atomicAdd(&g_count[dists[e]], 1);
}

__global__ void scan_kernel(int n) {
    __shared__ int sums[1024];
    int t = threadIdx.x;
    int ch = (n + 1023) / 1024;
    int beg = t * ch;
    int end = min(beg + ch, n);
    int s = 0;
    for (int i = beg; i < end; i++) s += g_count[i];
    sums[t] = s;
    __syncthreads();
    for (int off = 1; off < 1024; off <<= 1) {
        int v = (t >= off) ? sums[t - off] : 0;
        __syncthreads();
        sums[t] += v;
        __syncthreads();
    }
    int run = (t == 0) ? 0 : sums[t - 1];
    for (int i = beg; i < end; i++) {
        g_off[i] = run;
        g_cur[i] = run;
        run += g_count[i];
    }
    if (beg < n && end == n) g_off[n] = run;
}

__global__ void scatter_kernel(const int* __restrict__ sources,
                               const int* __restrict__ dists,
                               const float* __restrict__ weights, int E) {
    int e = blockIdx.x * blockDim.x + threadIdx.x;
    if (e >= E) return;
    int d = dists[e];
    int p = atomicAdd(&g_cur[d], 1);
    g_srcs[p] = sources[e];
    g_ws[p]   = weights[e];
}

// ============================================================
// Aggregation: one warp per node.
// agg[d] = (deg>0) ? P2b[d] + max_e( P1[src_e] + w_e * w_row ) : 0
// ============================================================
__global__ void agg_kernel(const float* __restrict__ Wm, int M) {
    int warp = (blockIdx.x * blockDim.x + threadIdx.x) >> 5;
    int lane = threadIdx.x & 31;
    if (warp >= M) return;

    int beg = g_off[warp];
    int end = g_off[warp + 1];

    const float4 wr = *(const float4*)(Wm + (size_t)256 * HID + lane * 4);

    const float NINF = __int_as_float(0xff800000);
    float4 acc = make_float4(NINF, NINF, NINF, NINF);

    for (int i = beg; i < end; i++) {
        int   s = g_srcs[i];
        float w = g_ws[i];
        const float4 p = *(const float4*)(g_P + (size_t)s * (2 * HID) + lane * 4);
        acc.x = fmaxf(acc.x, fmaf(w, wr.x, p.x));
        acc.y = fmaxf(acc.y, fmaf(w, wr.y, p.y));
        acc.z = fmaxf(acc.z, fmaf(w, wr.z, p.z));
        acc.w = fmaxf(acc.w, fmaf(w, wr.w, p.w));
    }

    float4 o;
    if (end > beg) {
        const float4 q = *(const float4*)(g_P + (size_t)warp * (2 * HID) + HID + lane * 4);
        o = make_float4(q.x + acc.x, q.y + acc.y, q.z + acc.z, q.w + acc.w);
    } else {
        o = make_float4(0.f, 0.f, 0.f, 0.f);
    }
    *(float4*)(g_agg + (size_t)warp * HID + lane * 4) = o;
}

// ============================================================
extern "C" void kernel_launch(void* const* d_in, const int* in_sizes, int n_in,
                              void* d_out, int out_size) {
    const float* z   = (const float*)d_in[0];
    const int*   src = (const int*)d_in[1];
    const int*   dst = (const int*)d_in[2];
    const float* w   = (const float*)d_in[3];
    const float* Wm  = (const float*)d_in[4];
    const float* bm  = (const float*)d_in[5];
    const float* Wu  = (const float*)d_in[6];
    const float* bu  = (const float*)d_in[7];
    float* out = (float*)d_out;

    int M = in_sizes[0] / HID;   // nodes
    int E = in_sizes[1];         // edges

    int nbm = (M + BM - 1) / BM;

    sgemm_proj<<<dim3(nbm, 2), 256>>>(z, Wm, bm, M);
    zero_counts<<<(M + 255) / 256, 256>>>(M);
    hist_kernel<<<(E + 255) / 256, 256>>>(dst, E);
    scan_kernel<<<1, 1024>>>(M);
    scatter_kernel<<<(E + 255) / 256, 256>>>(src, dst, w, E);
    {
        long long threads = (long long)M * 32;
        int blocks = (int)((threads + 255) / 256);
        agg_kernel<<<blocks, 256>>>(Wm, M);
    }
    sgemm_upd<<<nbm, 256>>>(z, Wu, bu, out, M);
}

// round 4
// speedup vs baseline: 1.4162x; 1.4162x over previous
#include <cuda_runtime.h>

#define HID 128
#define MAXN 50000
#define MAXE 640000

// ---- scratch (device globals: no allocation allowed) ----
__device__ __align__(16) float g_P[(size_t)MAXN * 2 * HID];   // [:,0:128]=z@W1, [:,128:256]=z@W2+b_msg
__device__ __align__(16) float g_agg[(size_t)MAXN * HID];
__device__ int   g_count[MAXN];
__device__ int   g_off[MAXN + 1];
__device__ int   g_cur[MAXN];
__device__ int   g_srcs[MAXE];
__device__ __align__(16) float g_ws[MAXE];
__device__ int   g_bsum[64];
__device__ int   g_boff[64];

#define BM 128
#define BN 128
#define BK 16
#define TM 8
#define TN 8

// packed fp32x2 FMA (Blackwell FFMA2 — ptxas never auto-fuses this)
__device__ __forceinline__ float2 ffma2(float2 a, float2 b, float2 c) {
    float2 d;
    asm("fma.rn.f32x2 %0, %1, %2, %3;"
        : "=l"(*reinterpret_cast<unsigned long long*>(&d))
        : "l"(*reinterpret_cast<unsigned long long*>(&a)),
          "l"(*reinterpret_cast<unsigned long long*>(&b)),
          "l"(*reinterpret_cast<unsigned long long*>(&c)));
    return d;
}

// ============================================================
// Projection GEMM: g_P[M,256] = z[M,128] @ [W1 | W2] (+ b_msg on right half)
// blockIdx.y = half. FFMA2 inner loop.
// ============================================================
__global__ void __launch_bounds__(256, 2) sgemm_proj(
    const float* __restrict__ z, const float* __restrict__ Wm,
    const float* __restrict__ bm, int M)
{
    __shared__ __align__(16) float As[BK][BM];
    __shared__ __align__(16) float Bs[BK][BN];

    const int m0   = blockIdx.x * BM;
    const int half = blockIdx.y;
    const float* B = Wm + (size_t)half * 128 * HID;

    const int t  = threadIdx.x;
    const int tx = t & 15;
    const int ty = t >> 4;

    const int a_row = t >> 2;
    const int a_col = (t & 3) * 4;
    const int b_row = t >> 5;
    const int b_col = (t & 31) * 4;

    float2 acc[TM][TN / 2];
#pragma unroll
    for (int i = 0; i < TM; i++)
#pragma unroll
        for (int j = 0; j < TN / 2; j++) acc[i][j] = make_float2(0.f, 0.f);

    for (int k0 = 0; k0 < HID; k0 += BK) {
#pragma unroll
        for (int r = 0; r < 2; r++) {
            int m = m0 + a_row + r * 64;
            float4 v = make_float4(0.f, 0.f, 0.f, 0.f);
            if (m < M) v = *(const float4*)(z + (size_t)m * HID + k0 + a_col);
            As[a_col + 0][a_row + r * 64] = v.x;
            As[a_col + 1][a_row + r * 64] = v.y;
            As[a_col + 2][a_row + r * 64] = v.z;
            As[a_col + 3][a_row + r * 64] = v.w;
        }
#pragma unroll
        for (int r = 0; r < 2; r++) {
            int k = k0 + b_row + r * 8;
            *(float4*)(&Bs[b_row + r * 8][b_col]) =
                *(const float4*)(B + (size_t)k * HID + b_col);
        }
        __syncthreads();

#pragma unroll
        for (int k = 0; k < BK; k++) {
            float ar[TM];
            *(float4*)&ar[0] = *(const float4*)&As[k][ty * TM];
            *(float4*)&ar[4] = *(const float4*)&As[k][ty * TM + 4];
            float4 b0 = *(const float4*)&Bs[k][tx * TN];
            float4 b1 = *(const float4*)&Bs[k][tx * TN + 4];
            float2 br[4] = {make_float2(b0.x, b0.y), make_float2(b0.z, b0.w),
                            make_float2(b1.x, b1.y), make_float2(b1.z, b1.w)};
#pragma unroll
            for (int i = 0; i < TM; i++) {
                float2 ai = make_float2(ar[i], ar[i]);
#pragma unroll
                for (int j = 0; j < TN / 2; j++)
                    acc[i][j] = ffma2(ai, br[j], acc[i][j]);
            }
        }
        __syncthreads();
    }

#pragma unroll
    for (int i = 0; i < TM; i++) {
        int m = m0 + ty * TM + i;
        if (m >= M) continue;
#pragma unroll
        for (int j = 0; j < TN / 2; j++) {
            int col = tx * TN + 2 * j;
            float2 v = acc[i][j];
            if (half) { v.x += bm[col]; v.y += bm[col + 1]; }
            *(float2*)(g_P + (size_t)m * (2 * HID) + half * HID + col) = v;
        }
    }
}

// ============================================================
// Update GEMM: out[M,128] = [z | agg][M,256] @ W_upd[256,128] + b_upd
// ============================================================
__global__ void __launch_bounds__(256, 2) sgemm_upd(
    const float* __restrict__ z, const float* __restrict__ Wu,
    const float* __restrict__ bu, float* __restrict__ out, int M)
{
    __shared__ __align__(16) float As[BK][BM];
    __shared__ __align__(16) float Bs[BK][BN];

    const int m0 = blockIdx.x * BM;
    const int t  = threadIdx.x;
    const int tx = t & 15;
    const int ty = t >> 4;

    const int a_row = t >> 2;
    const int a_col = (t & 3) * 4;
    const int b_row = t >> 5;
    const int b_col = (t & 31) * 4;

    float2 acc[TM][TN / 2];
#pragma unroll
    for (int i = 0; i < TM; i++)
#pragma unroll
        for (int j = 0; j < TN / 2; j++) acc[i][j] = make_float2(0.f, 0.f);

    for (int k0 = 0; k0 < 2 * HID; k0 += BK) {
        const float* Asrc = (k0 < HID) ? z : g_agg;
        int kbase = (k0 < HID) ? k0 : (k0 - HID);
#pragma unroll
        for (int r = 0; r < 2; r++) {
            int m = m0 + a_row + r * 64;
            float4 v = make_float4(0.f, 0.f, 0.f, 0.f);
            if (m < M) v = *(const float4*)(Asrc + (size_t)m * HID + kbase + a_col);
            As[a_col + 0][a_row + r * 64] = v.x;
            As[a_col + 1][a_row + r * 64] = v.y;
            As[a_col + 2][a_row + r * 64] = v.z;
            As[a_col + 3][a_row + r * 64] = v.w;
        }
#pragma unroll
        for (int r = 0; r < 2; r++) {
            int k = k0 + b_row + r * 8;
            *(float4*)(&Bs[b_row + r * 8][b_col]) =
                *(const float4*)(Wu + (size_t)k * HID + b_col);
        }
        __syncthreads();

#pragma unroll
        for (int k = 0; k < BK; k++) {
            float ar[TM];
            *(float4*)&ar[0] = *(const float4*)&As[k][ty * TM];
            *(float4*)&ar[4] = *(const float4*)&As[k][ty * TM + 4];
            float4 b0 = *(const float4*)&Bs[k][tx * TN];
            float4 b1 = *(const float4*)&Bs[k][tx * TN + 4];
            float2 br[4] = {make_float2(b0.x, b0.y), make_float2(b0.z, b0.w),
                            make_float2(b1.x, b1.y), make_float2(b1.z, b1.w)};
#pragma unroll
            for (int i = 0; i < TM; i++) {
                float2 ai = make_float2(ar[i], ar[i]);
#pragma unroll
                for (int j = 0; j < TN / 2; j++)
                    acc[i][j] = ffma2(ai, br[j], acc[i][j]);
            }
        }
        __syncthreads();
    }

#pragma unroll
    for (int i = 0; i < TM; i++) {
        int m = m0 + ty * TM + i;
        if (m >= M) continue;
#pragma unroll
        for (int j = 0; j < TN / 2; j++) {
            int col = tx * TN + 2 * j;
            float2 v = acc[i][j];
            v.x += bu[col];
            v.y += bu[col + 1];
            *(float2*)(out + (size_t)m * HID + col) = v;
        }
    }
}

// ============================================================
// CSR build: zero -> histogram -> 3-phase parallel scan -> scatter
// ============================================================
__global__ void zero_counts(int n) {
    int i = blockIdx.x * blockDim.x + threadIdx.x;
    if (i < n) g_count[i] = 0;
}

__global__ void hist_kernel(const int* __restrict__ dists, int E) {
    int e = blockIdx.x * blockDim.x + threadIdx.x;
    if (e < E) atomicAdd(&g_count[dists[e]], 1);
}

#define SCAN_BLK 256
#define SCAN_CHUNK 1024

// phase 1: per-block (1024-element chunk) sum
__global__ void scan_reduce(int M) {
    __shared__ int sdata[SCAN_BLK];
    int base = blockIdx.x * SCAN_CHUNK;
    int t = threadIdx.x;
    int s = 0;
#pragma unroll
    for (int i = 0; i < 4; i++) {
        int idx = base + t + i * SCAN_BLK;
        if (idx < M) s += g_count[idx];
    }
    sdata[t] = s;
    __syncthreads();
    for (int off = 128; off > 0; off >>= 1) {
        if (t < off) sdata[t] += sdata[t + off];
        __syncthreads();
    }
    if (t == 0) g_bsum[blockIdx.x] = sdata[0];
}

// phase 2: exclusive scan of up to 64 block sums (single tiny block)
__global__ void scan_partials(int nblk) {
    __shared__ int sh[64];
    int t = threadIdx.x;
    int v = (t < nblk) ? g_bsum[t] : 0;
    sh[t] = v;
    __syncthreads();
    for (int off = 1; off < 64; off <<= 1) {
        int u = (t >= off) ? sh[t - off] : 0;
        __syncthreads();
        sh[t] += u;
        __syncthreads();
    }
    if (t < nblk) g_boff[t] = (t == 0) ? 0 : sh[t - 1];
}

// phase 3: per-chunk exclusive scan + apply block offset
__global__ void scan_final(int M) {
    __shared__ int warpsums[SCAN_BLK / 32];
    int base = blockIdx.x * SCAN_CHUNK;
    int t = threadIdx.x;
    int lane = t & 31, wid = t >> 5;

    int idx0 = base + t * 4;
    int c[4];
#pragma unroll
    for (int i = 0; i < 4; i++) c[i] = (idx0 + i < M) ? g_count[idx0 + i] : 0;
    int tsum = c[0] + c[1] + c[2] + c[3];

    int v = tsum;
#pragma unroll
    for (int off = 1; off < 32; off <<= 1) {
        int u = __shfl_up_sync(0xffffffff, v, off);
        if (lane >= off) v += u;
    }
    if (lane == 31) warpsums[wid] = v;
    __syncthreads();
    if (wid == 0) {
        int wv = (lane < SCAN_BLK / 32) ? warpsums[lane] : 0;
#pragma unroll
        for (int off = 1; off < 8; off <<= 1) {
            int u = __shfl_up_sync(0xffffffff, wv, off);
            if (lane >= off) wv += u;
        }
        if (lane < SCAN_BLK / 32) warpsums[lane] = wv;
    }
    __syncthreads();

    int excl = v - tsum + (wid ? warpsums[wid - 1] : 0) + g_boff[blockIdx.x];
    int run = excl;
#pragma unroll
    for (int i = 0; i < 4; i++) {
        int idx = idx0 + i;
        if (idx < M) {
            g_off[idx] = run;
            g_cur[idx] = run;
            run += c[i];
            if (idx == M - 1) g_off[M] = run;
        }
    }
}

__global__ void scatter_kernel(const int* __restrict__ sources,
                               const int* __restrict__ dists,
                               const float* __restrict__ weights, int E) {
    int e = blockIdx.x * blockDim.x + threadIdx.x;
    if (e >= E) return;
    int d = dists[e];
    int p = atomicAdd(&g_cur[d], 1);
    g_srcs[p] = sources[e];
    g_ws[p]   = weights[e];
}

// ============================================================
// Aggregation: one warp per node.
// agg[d] = (deg>0) ? P2b[d] + max_e( P1[src_e] + w_e * w_row ) : 0
// ============================================================
__global__ void agg_kernel(const float* __restrict__ Wm, int M) {
    int warp = (blockIdx.x * blockDim.x + threadIdx.x) >> 5;
    int lane = threadIdx.x & 31;
    if (warp >= M) return;

    int beg = g_off[warp];
    int end = g_off[warp + 1];

    const float4 wr = *(const float4*)(Wm + (size_t)256 * HID + lane * 4);

    const float NINF = __int_as_float(0xff800000);
    float4 acc = make_float4(NINF, NINF, NINF, NINF);

    for (int i = beg; i < end; i++) {
        int   s = g_srcs[i];
        float w = g_ws[i];
        const float4 p = *(const float4*)(g_P + (size_t)s * (2 * HID) + lane * 4);
        acc.x = fmaxf(acc.x, fmaf(w, wr.x, p.x));
        acc.y = fmaxf(acc.y, fmaf(w, wr.y, p.y));
        acc.z = fmaxf(acc.z, fmaf(w, wr.z, p.z));
        acc.w = fmaxf(acc.w, fmaf(w, wr.w, p.w));
    }

    float4 o;
    if (end > beg) {
        const float4 q = *(const float4*)(g_P + (size_t)warp * (2 * HID) + HID + lane * 4);
        o = make_float4(q.x + acc.x, q.y + acc.y, q.z + acc.z, q.w + acc.w);
    } else {
        o = make_float4(0.f, 0.f, 0.f, 0.f);
    }
    *(float4*)(g_agg + (size_t)warp * HID + lane * 4) = o;
}

// ============================================================
extern "C" void kernel_launch(void* const* d_in, const int* in_sizes, int n_in,
                              void* d_out, int out_size) {
    const float* z   = (const float*)d_in[0];
    const int*   src = (const int*)d_in[1];
    const int*   dst = (const int*)d_in[2];
    const float* w   = (const float*)d_in[3];
    const float* Wm  = (const float*)d_in[4];
    const float* bm  = (const float*)d_in[5];
    const float* Wu  = (const float*)d_in[6];
    const float* bu  = (const float*)d_in[7];
    float* out = (float*)d_out;

    int M = in_sizes[0] / HID;   // nodes
    int E = in_sizes[1];         // edges

    int nbm = (M + BM - 1) / BM;
    int nchunk = (M + SCAN_CHUNK - 1) / SCAN_CHUNK;

    sgemm_proj<<<dim3(nbm, 2), 256>>>(z, Wm, bm, M);
    zero_counts<<<(M + 255) / 256, 256>>>(M);
    hist_kernel<<<(E + 255) / 256, 256>>>(dst, E);
    scan_reduce<<<nchunk, SCAN_BLK>>>(M);
    scan_partials<<<1, 64>>>(nchunk);
    scan_final<<<nchunk, SCAN_BLK>>>(M);
    scatter_kernel<<<(E + 255) / 256, 256>>>(src, dst, w, E);
    {
        long long threads = (long long)M * 32;
        int blocks = (int)((threads + 255) / 256);
        agg_kernel<<<blocks, 256>>>(Wm, M);
    }
    sgemm_upd<<<nbm, 256>>>(z, Wu, bu, out, M);
}

// round 12
// speedup vs baseline: 2.1378x; 1.5095x over previous
#include <cuda_runtime.h>
#include <cuda_bf16.h>
#include <cstdint>

#define HID 128
#define MAXN 50000
#define MAXE 640000
#define LDS 136   // padded SMEM row stride in bf16 elements (conflict-free frag loads)

// ---- scratch (device globals: no allocation allowed) ----
__device__ __align__(16) float g_P[(size_t)MAXN * 2 * HID];   // [:,0:128]=z@W1, [:,128:256]=z@W2+b_msg
__device__ __align__(16) float g_agg[(size_t)MAXN * HID];
__device__ int   g_count[MAXN];
__device__ int   g_off[MAXN + 1];
__device__ int   g_cur[MAXN];
__device__ int   g_srcs[MAXE];
__device__ __align__(16) float g_ws[MAXE];
__device__ int   g_bsum[64];
__device__ int   g_boff[64];

// pre-converted weight tiles: 4 tiles of [N=128][K=128] bf16 hi/lo, packed as
// u32 pairs along K: g_B*[tile*8192 + n*64 + k/2]
// tile 0: Wm rows 0..127 | 1: Wm rows 128..255 | 2: Wu rows 0..127 | 3: Wu rows 128..255
__device__ __align__(16) uint32_t g_Bhi[4 * 8192];
__device__ __align__(16) uint32_t g_Blo[4 * 8192];

// ============================================================
// helpers
// ============================================================

// split two floats into packed bf16x2 hi parts and bf16x2 lo parts
// (lo = x - bf16(x)); result u32 has element x in low half, y in high half
__device__ __forceinline__ void split2(float x, float y, uint32_t& h2, uint32_t& l2) {
    asm("cvt.rn.bf16x2.f32 %0, %1, %2;" : "=r"(h2) : "f"(y), "f"(x));
    float xh = __uint_as_float(h2 << 16);
    float yh = __uint_as_float(h2 & 0xFFFF0000u);
    float xl = x - xh;
    float yl = y - yh;
    asm("cvt.rn.bf16x2.f32 %0, %1, %2;" : "=r"(l2) : "f"(yl), "f"(xl));
}

// m16n8k16 bf16 MMA, fp32 accumulate (baseline PTX, sm_80+; no arch suffix)
__device__ __forceinline__ void mma16816(float* c, const uint32_t* a, uint32_t b0, uint32_t b1) {
    asm volatile(
        "mma.sync.aligned.m16n8k16.row.col.f32.bf16.bf16.f32 "
        "{%0,%1,%2,%3}, {%4,%5,%6,%7}, {%8,%9}, {%0,%1,%2,%3};"
        : "+f"(c[0]), "+f"(c[1]), "+f"(c[2]), "+f"(c[3])
        : "r"(a[0]), "r"(a[1]), "r"(a[2]), "r"(a[3]), "r"(b0), "r"(b1));
}

// ============================================================
// prep_w: W[k][n] (row-major [K,N]) -> transposed [N][K] bf16 hi/lo, packed u32
// ============================================================
__global__ void prep_w(const float* __restrict__ Wm, const float* __restrict__ Wu) {
    int idx = blockIdx.x * blockDim.x + threadIdx.x;   // 0 .. 32767
    int tile = idx >> 13;
    int r = idx & 8191;
    int n = r >> 6;
    int k = (r & 63) * 2;
    const float* W = (tile < 2) ? Wm : Wu;
    int krow = (tile & 1) * 128 + k;
    float x = W[(size_t)krow * HID + n];
    float y = W[(size_t)(krow + 1) * HID + n];
    uint32_t h2, l2;
    split2(x, y, h2, l2);
    g_Bhi[idx] = h2;
    g_Blo[idx] = l2;
}

// ============================================================
// mma_gemm: out[m, col0+0..127] (+bias) = sum over KT K-tiles of A_kt @ Btile^T
// CTA tile 128x128, 8 warps as 4(M) x 2(N), warp tile 32x64.
// A fp32 -> bf16 hi/lo split in SMEM; 3 passes (hh, hl, lh) accumulate in regs.
// K-tile 0 reads A0 (input pointer); K-tile 1 (upd only) reads g_agg,
// resolved DEVICE-side (passing __device__ symbols from host is invalid).
// out_is_P: write g_P (device-resolved) instead of the out_ext pointer.
// proj_mode: gridDim.y=2 selects B tile & output half; bias only on half 1.
// ============================================================
#define SMEM_A_HI 0
#define SMEM_A_LO (128 * LDS * 2)
#define SMEM_B_HI (2 * 128 * LDS * 2)
#define SMEM_B_LO (3 * 128 * LDS * 2)
#define SMEM_SZ   (4 * 128 * LDS * 2)

__global__ void __launch_bounds__(256, 1) mma_gemm(
    const float* __restrict__ A0,
    int bt0, const float* __restrict__ bias,
    float* __restrict__ out_ext, int out_is_P,
    int out_stride, int proj_mode, int KT, int M)
{
    extern __shared__ char sm[];
    const int tid  = threadIdx.x;
    const int wid  = tid >> 5;
    const int lane = tid & 31;
    const int g    = lane >> 2;   // group id 0..7
    const int t4   = lane & 3;    // thread-in-group 0..3
    const int wm   = (wid >> 1) * 32;  // warp M offset within CTA tile
    const int wn   = (wid & 1) * 64;   // warp N offset within CTA tile
    const int m0   = blockIdx.x * 128;

    float* out = out_is_P ? g_P : out_ext;

    float acc[2][8][4];
#pragma unroll
    for (int i = 0; i < 2; i++)
#pragma unroll
        for (int j = 0; j < 8; j++)
#pragma unroll
            for (int q = 0; q < 4; q++) acc[i][j][q] = 0.0f;

    for (int kt = 0; kt < KT; kt++) {
        const float* A = kt ? (const float*)g_agg : A0;   // device-side symbol ref
        int tile = proj_mode ? (int)blockIdx.y : (bt0 + kt);

        // stage B tile [128n x 128k] bf16 hi/lo into padded SMEM
        {
            const uint4* bh = (const uint4*)(g_Bhi + (size_t)tile * 8192);
            const uint4* bl = (const uint4*)(g_Blo + (size_t)tile * 8192);
            for (int i = tid; i < 2048; i += 256) {
                int n  = i >> 4;
                int ke = (i & 15) * 8;     // element k offset (8 bf16 per uint4)
                *(uint4*)(sm + SMEM_B_HI + (n * LDS + ke) * 2) = bh[i];
                *(uint4*)(sm + SMEM_B_LO + (n * LDS + ke) * 2) = bl[i];
            }
        }
        // stage + split A tile [128m x 128k]
        for (int i = tid; i < 4096; i += 256) {
            int ml = i >> 5;
            int k0 = (i & 31) * 4;
            int m = m0 + ml;
            float4 v = make_float4(0.f, 0.f, 0.f, 0.f);
            if (m < M) v = *(const float4*)(A + (size_t)m * HID + k0);
            uint32_t h0, l0, h1, l1;
            split2(v.x, v.y, h0, l0);
            split2(v.z, v.w, h1, l1);
            *(uint2*)(sm + SMEM_A_HI + (ml * LDS + k0) * 2) = make_uint2(h0, h1);
            *(uint2*)(sm + SMEM_A_LO + (ml * LDS + k0) * 2) = make_uint2(l0, l1);
        }
        __syncthreads();

#pragma unroll 1
        for (int kk = 0; kk < 8; kk++) {
            const int k0 = kk * 16;
            uint32_t ah[2][4], al[2][4];
#pragma unroll
            for (int i = 0; i < 2; i++) {
                int r0 = wm + i * 16 + g;
                int r1 = r0 + 8;
                ah[i][0] = *(const uint32_t*)(sm + SMEM_A_HI + (r0 * LDS + k0 + 2 * t4) * 2);
                ah[i][1] = *(const uint32_t*)(sm + SMEM_A_HI + (r1 * LDS + k0 + 2 * t4) * 2);
                ah[i][2] = *(const uint32_t*)(sm + SMEM_A_HI + (r0 * LDS + k0 + 8 + 2 * t4) * 2);
                ah[i][3] = *(const uint32_t*)(sm + SMEM_A_HI + (r1 * LDS + k0 + 8 + 2 * t4) * 2);
            }
            // pass 0: A_hi x B_hi
#pragma unroll
            for (int j = 0; j < 8; j++) {
                int n = wn + j * 8 + g;
                uint32_t b0 = *(const uint32_t*)(sm + SMEM_B_HI + (n * LDS + k0 + 2 * t4) * 2);
                uint32_t b1 = *(const uint32_t*)(sm + SMEM_B_HI + (n * LDS + k0 + 8 + 2 * t4) * 2);
                mma16816(acc[0][j], ah[0], b0, b1);
                mma16816(acc[1][j], ah[1], b0, b1);
            }
            // pass 1: A_hi x B_lo
#pragma unroll
            for (int j = 0; j < 8; j++) {
                int n = wn + j * 8 + g;
                uint32_t b0 = *(const uint32_t*)(sm + SMEM_B_LO + (n * LDS + k0 + 2 * t4) * 2);
                uint32_t b1 = *(const uint32_t*)(sm + SMEM_B_LO + (n * LDS + k0 + 8 + 2 * t4) * 2);
                mma16816(acc[0][j], ah[0], b0, b1);
                mma16816(acc[1][j], ah[1], b0, b1);
            }
            // pass 2: A_lo x B_hi
#pragma unroll
            for (int i = 0; i < 2; i++) {
                int r0 = wm + i * 16 + g;
                int r1 = r0 + 8;
                al[i][0] = *(const uint32_t*)(sm + SMEM_A_LO + (r0 * LDS + k0 + 2 * t4) * 2);
                al[i][1] = *(const uint32_t*)(sm + SMEM_A_LO + (r1 * LDS + k0 + 2 * t4) * 2);
                al[i][2] = *(const uint32_t*)(sm + SMEM_A_LO + (r0 * LDS + k0 + 8 + 2 * t4) * 2);
                al[i][3] = *(const uint32_t*)(sm + SMEM_A_LO + (r1 * LDS + k0 + 8 + 2 * t4) * 2);
            }
#pragma unroll
            for (int j = 0; j < 8; j++) {
                int n = wn + j * 8 + g;
                uint32_t b0 = *(const uint32_t*)(sm + SMEM_B_HI + (n * LDS + k0 + 2 * t4) * 2);
                uint32_t b1 = *(const uint32_t*)(sm + SMEM_B_HI + (n * LDS + k0 + 8 + 2 * t4) * 2);
                mma16816(acc[0][j], al[0], b0, b1);
                mma16816(acc[1][j], al[1], b0, b1);
            }
        }
        __syncthreads();
    }

    // epilogue: thread owns rows (g, g+8) per m-frag, cols 2t,2t+1 per n-frag
    const int col0 = proj_mode ? (int)blockIdx.y * 128 : 0;
    const bool useb = bias && (!proj_mode || blockIdx.y == 1);
#pragma unroll
    for (int i = 0; i < 2; i++) {
        int r0 = m0 + wm + i * 16 + g;
        int r1 = r0 + 8;
#pragma unroll
        for (int j = 0; j < 8; j++) {
            int c = wn + j * 8 + 2 * t4;
            float b0v = 0.f, b1v = 0.f;
            if (useb) { b0v = bias[c]; b1v = bias[c + 1]; }
            if (r0 < M)
                *(float2*)(out + (size_t)r0 * out_stride + col0 + c) =
                    make_float2(acc[i][j][0] + b0v, acc[i][j][1] + b1v);
            if (r1 < M)
                *(float2*)(out + (size_t)r1 * out_stride + col0 + c) =
                    make_float2(acc[i][j][2] + b0v, acc[i][j][3] + b1v);
        }
    }
}

// ============================================================
// CSR build: zero -> histogram -> 3-phase parallel scan -> scatter
// ============================================================
__global__ void zero_counts(int n) {
    int i = blockIdx.x * blockDim.x + threadIdx.x;
    if (i < n) g_count[i] = 0;
}

__global__ void hist_kernel(const int* __restrict__ dists, int E) {
    int e = blockIdx.x * blockDim.x + threadIdx.x;
    if (e < E) atomicAdd(&g_count[dists[e]], 1);
}

#define SCAN_BLK 256
#define SCAN_CHUNK 1024

__global__ void scan_reduce(int M) {
    __shared__ int sdata[SCAN_BLK];
    int base = blockIdx.x * SCAN_CHUNK;
    int t = threadIdx.x;
    int s = 0;
#pragma unroll
    for (int i = 0; i < 4; i++) {
        int idx = base + t + i * SCAN_BLK;
        if (idx < M) s += g_count[idx];
    }
    sdata[t] = s;
    __syncthreads();
    for (int off = 128; off > 0; off >>= 1) {
        if (t < off) sdata[t] += sdata[t + off];
        __syncthreads();
    }
    if (t == 0) g_bsum[blockIdx.x] = sdata[0];
}

__global__ void scan_partials(int nblk) {
    __shared__ int sh[64];
    int t = threadIdx.x;
    int v = (t < nblk) ? g_bsum[t] : 0;
    sh[t] = v;
    __syncthreads();
    for (int off = 1; off < 64; off <<= 1) {
        int u = (t >= off) ? sh[t - off] : 0;
        __syncthreads();
        sh[t] += u;
        __syncthreads();
    }
    if (t < nblk) g_boff[t] = (t == 0) ? 0 : sh[t - 1];
}

__global__ void scan_final(int M) {
    __shared__ int warpsums[SCAN_BLK / 32];
    int base = blockIdx.x * SCAN_CHUNK;
    int t = threadIdx.x;
    int lane = t & 31, wid = t >> 5;

    int idx0 = base + t * 4;
    int c[4];
#pragma unroll
    for (int i = 0; i < 4; i++) c[i] = (idx0 + i < M) ? g_count[idx0 + i] : 0;
    int tsum = c[0] + c[1] + c[2] + c[3];

    int v = tsum;
#pragma unroll
    for (int off = 1; off < 32; off <<= 1) {
        int u = __shfl_up_sync(0xffffffff, v, off);
        if (lane >= off) v += u;
    }
    if (lane == 31) warpsums[wid] = v;
    __syncthreads();
    if (wid == 0) {
        int wv = (lane < SCAN_BLK / 32) ? warpsums[lane] : 0;
#pragma unroll
        for (int off = 1; off < 8; off <<= 1) {
            int u = __shfl_up_sync(0xffffffff, wv, off);
            if (lane >= off) wv += u;
        }
        if (lane < SCAN_BLK / 32) warpsums[lane] = wv;
    }
    __syncthreads();

    int excl = v - tsum + (wid ? warpsums[wid - 1] : 0) + g_boff[blockIdx.x];
    int run = excl;
#pragma unroll
    for (int i = 0; i < 4; i++) {
        int idx = idx0 + i;
        if (idx < M) {
            g_off[idx] = run;
            g_cur[idx] = run;
            run += c[i];
            if (idx == M - 1) g_off[M] = run;
        }
    }
}

__global__ void scatter_kernel(const int* __restrict__ sources,
                               const int* __restrict__ dists,
                               const float* __restrict__ weights, int E) {
    int e = blockIdx.x * blockDim.x + threadIdx.x;
    if (e >= E) return;
    int d = dists[e];
    int p = atomicAdd(&g_cur[d], 1);
    g_srcs[p] = sources[e];
    g_ws[p]   = weights[e];
}

// ============================================================
// Aggregation: one warp per node.
// agg[d] = (deg>0) ? P2b[d] + max_e( P1[src_e] + w_e * w_row ) : 0
// ============================================================
__global__ void agg_kernel(const float* __restrict__ Wm, int M) {
    int warp = (blockIdx.x * blockDim.x + threadIdx.x) >> 5;
    int lane = threadIdx.x & 31;
    if (warp >= M) return;

    int beg = g_off[warp];
    int end = g_off[warp + 1];

    const float4 wr = *(const float4*)(Wm + (size_t)256 * HID + lane * 4);

    const float NINF = __int_as_float(0xff800000);
    float4 acc = make_float4(NINF, NINF, NINF, NINF);

    for (int i = beg; i < end; i++) {
        int   s = g_srcs[i];
        float w = g_ws[i];
        const float4 p = *(const float4*)(g_P + (size_t)s * (2 * HID) + lane * 4);
        acc.x = fmaxf(acc.x, fmaf(w, wr.x, p.x));
        acc.y = fmaxf(acc.y, fmaf(w, wr.y, p.y));
        acc.z = fmaxf(acc.z, fmaf(w, wr.z, p.z));
        acc.w = fmaxf(acc.w, fmaf(w, wr.w, p.w));
    }

    float4 o;
    if (end > beg) {
        const float4 q = *(const float4*)(g_P + (size_t)warp * (2 * HID) + HID + lane * 4);
        o = make_float4(q.x + acc.x, q.y + acc.y, q.z + acc.z, q.w + acc.w);
    } else {
        o = make_float4(0.f, 0.f, 0.f, 0.f);
    }
    *(float4*)(g_agg + (size_t)warp * HID + lane * 4) = o;
}

// ============================================================
extern "C" void kernel_launch(void* const* d_in, const int* in_sizes, int n_in,
                              void* d_out, int out_size) {
    const float* z   = (const float*)d_in[0];
    const int*   src = (const int*)d_in[1];
    const int*   dst = (const int*)d_in[2];
    const float* w   = (const float*)d_in[3];
    const float* Wm  = (const float*)d_in[4];
    const float* bm  = (const float*)d_in[5];
    const float* Wu  = (const float*)d_in[6];
    const float* bu  = (const float*)d_in[7];
    float* out = (float*)d_out;

    int M = in_sizes[0] / HID;   // nodes
    int E = in_sizes[1];         // edges

    int nbm = (M + 127) / 128;
    int nchunk = (M + SCAN_CHUNK - 1) / SCAN_CHUNK;

    static int smem_set = 0;
    if (!smem_set) {
        cudaFuncSetAttribute(mma_gemm, cudaFuncAttributeMaxDynamicSharedMemorySize, SMEM_SZ);
        smem_set = 1;
    }

    prep_w<<<128, 256>>>(Wm, Wu);
    // proj: g_P[m, half*128 + c] (device-resolved), B tiles 0/1, bias bm on half 1
    mma_gemm<<<dim3(nbm, 2), 256, SMEM_SZ>>>(z, 0, bm, nullptr, 1, 2 * HID, 1, 1, M);
    zero_counts<<<(M + 255) / 256, 256>>>(M);
    hist_kernel<<<(E + 255) / 256, 256>>>(dst, E);
    scan_reduce<<<nchunk, SCAN_BLK>>>(M);
    scan_partials<<<1, 64>>>(nchunk);
    scan_final<<<nchunk, SCAN_BLK>>>(M);
    scatter_kernel<<<(E + 255) / 256, 256>>>(src, dst, w, E);
    {
        long long threads = (long long)M * 32;
        int blocks = (int)((threads + 255) / 256);
        agg_kernel<<<blocks, 256>>>(Wm, M);
    }
    // upd: out = [z | agg] @ Wu + bu, B tiles 2/3 (K-tile 1 reads g_agg device-side)
    mma_gemm<<<nbm, 256, SMEM_SZ>>>(z, 2, bu, out, 0, HID, 0, 2, M);
}

// round 13
// speedup vs baseline: 2.2731x; 1.0633x over previous
#include <cuda_runtime.h>
#include <cuda_bf16.h>
#include <cstdint>

#define HID 128
#define MAXN 50000
#define MAXE 640000
#define LDS 136   // padded SMEM row stride in bf16 elements (conflict-free frag loads)

// ---- scratch (device globals: no allocation allowed) ----
__device__ __align__(16) float g_P[(size_t)MAXN * 2 * HID];   // [:,0:128]=z@W1, [:,128:256]=z@W2+b_msg
__device__ __align__(16) float g_agg[(size_t)MAXN * HID];
__device__ int   g_count[MAXN];
__device__ int   g_off[MAXN + 1];
__device__ int   g_cur[MAXN];
__device__ __align__(16) int2 g_edge[MAXE];   // packed (src, w_bits) per CSR slot
__device__ int   g_bsum[64];
__device__ int   g_boff[64];

// pre-converted weight tiles: 4 tiles of [N=128][K=128] bf16 hi/lo, packed as
// u32 pairs along K: g_B*[tile*8192 + n*64 + k/2]
// tile 0: Wm rows 0..127 | 1: Wm rows 128..255 | 2: Wu rows 0..127 | 3: Wu rows 128..255
__device__ __align__(16) uint32_t g_Bhi[4 * 8192];
__device__ __align__(16) uint32_t g_Blo[4 * 8192];

// ============================================================
// helpers
// ============================================================

// split two floats into packed bf16x2 hi parts and bf16x2 lo parts
// (lo = x - bf16(x)); result u32 has element x in low half, y in high half
__device__ __forceinline__ void split2(float x, float y, uint32_t& h2, uint32_t& l2) {
    asm("cvt.rn.bf16x2.f32 %0, %1, %2;" : "=r"(h2) : "f"(y), "f"(x));
    float xh = __uint_as_float(h2 << 16);
    float yh = __uint_as_float(h2 & 0xFFFF0000u);
    float xl = x - xh;
    float yl = y - yh;
    asm("cvt.rn.bf16x2.f32 %0, %1, %2;" : "=r"(l2) : "f"(yl), "f"(xl));
}

// m16n8k16 bf16 MMA, fp32 accumulate (baseline PTX, sm_80+; no arch suffix)
__device__ __forceinline__ void mma16816(float* c, const uint32_t* a, uint32_t b0, uint32_t b1) {
    asm volatile(
        "mma.sync.aligned.m16n8k16.row.col.f32.bf16.bf16.f32 "
        "{%0,%1,%2,%3}, {%4,%5,%6,%7}, {%8,%9}, {%0,%1,%2,%3};"
        : "+f"(c[0]), "+f"(c[1]), "+f"(c[2]), "+f"(c[3])
        : "r"(a[0]), "r"(a[1]), "r"(a[2]), "r"(a[3]), "r"(b0), "r"(b1));
}

// ============================================================
// prep_w: W[k][n] (row-major [K,N]) -> transposed [N][K] bf16 hi/lo, packed u32
// ============================================================
__global__ void prep_w(const float* __restrict__ Wm, const float* __restrict__ Wu) {
    int idx = blockIdx.x * blockDim.x + threadIdx.x;   // 0 .. 32767
    int tile = idx >> 13;
    int r = idx & 8191;
    int n = r >> 6;
    int k = (r & 63) * 2;
    const float* W = (tile < 2) ? Wm : Wu;
    int krow = (tile & 1) * 128 + k;
    float x = W[(size_t)krow * HID + n];
    float y = W[(size_t)(krow + 1) * HID + n];
    uint32_t h2, l2;
    split2(x, y, h2, l2);
    g_Bhi[idx] = h2;
    g_Blo[idx] = l2;
}

// ============================================================
// mma_gemm: out[m, col0+0..127] (+bias) = sum over KT K-tiles of A_kt @ Btile^T
// CTA tile 128x128, 8 warps as 4(M) x 2(N), warp tile 32x64.
// A fp32 -> bf16 hi/lo split in SMEM; 3 passes (hh, hl, lh) accumulate in regs.
// K-tile 0 reads A0 (input pointer); K-tile 1 (upd only) reads g_agg,
// resolved DEVICE-side (passing __device__ symbols from host is invalid).
// out_is_P: write g_P (device-resolved) instead of the out_ext pointer.
// proj_mode: gridDim.y=2 selects B tile & output half; bias only on half 1.
// ============================================================
#define SMEM_A_HI 0
#define SMEM_A_LO (128 * LDS * 2)
#define SMEM_B_HI (2 * 128 * LDS * 2)
#define SMEM_B_LO (3 * 128 * LDS * 2)
#define SMEM_SZ   (4 * 128 * LDS * 2)

__global__ void __launch_bounds__(256, 1) mma_gemm(
    const float* __restrict__ A0,
    int bt0, const float* __restrict__ bias,
    float* __restrict__ out_ext, int out_is_P,
    int out_stride, int proj_mode, int KT, int M)
{
    extern __shared__ char sm[];
    const int tid  = threadIdx.x;
    const int wid  = tid >> 5;
    const int lane = tid & 31;
    const int g    = lane >> 2;   // group id 0..7
    const int t4   = lane & 3;    // thread-in-group 0..3
    const int wm   = (wid >> 1) * 32;  // warp M offset within CTA tile
    const int wn   = (wid & 1) * 64;   // warp N offset within CTA tile
    const int m0   = blockIdx.x * 128;

    float* out = out_is_P ? g_P : out_ext;

    float acc[2][8][4];
#pragma unroll
    for (int i = 0; i < 2; i++)
#pragma unroll
        for (int j = 0; j < 8; j++)
#pragma unroll
            for (int q = 0; q < 4; q++) acc[i][j][q] = 0.0f;

    for (int kt = 0; kt < KT; kt++) {
        const float* A = kt ? (const float*)g_agg : A0;   // device-side symbol ref
        int tile = proj_mode ? (int)blockIdx.y : (bt0 + kt);

        // stage B tile [128n x 128k] bf16 hi/lo into padded SMEM
        {
            const uint4* bh = (const uint4*)(g_Bhi + (size_t)tile * 8192);
            const uint4* bl = (const uint4*)(g_Blo + (size_t)tile * 8192);
            for (int i = tid; i < 2048; i += 256) {
                int n  = i >> 4;
                int ke = (i & 15) * 8;     // element k offset (8 bf16 per uint4)
                *(uint4*)(sm + SMEM_B_HI + (n * LDS + ke) * 2) = bh[i];
                *(uint4*)(sm + SMEM_B_LO + (n * LDS + ke) * 2) = bl[i];
            }
        }
        // stage + split A tile [128m x 128k]
        for (int i = tid; i < 4096; i += 256) {
            int ml = i >> 5;
            int k0 = (i & 31) * 4;
            int m = m0 + ml;
            float4 v = make_float4(0.f, 0.f, 0.f, 0.f);
            if (m < M) v = *(const float4*)(A + (size_t)m * HID + k0);
            uint32_t h0, l0, h1, l1;
            split2(v.x, v.y, h0, l0);
            split2(v.z, v.w, h1, l1);
            *(uint2*)(sm + SMEM_A_HI + (ml * LDS + k0) * 2) = make_uint2(h0, h1);
            *(uint2*)(sm + SMEM_A_LO + (ml * LDS + k0) * 2) = make_uint2(l0, l1);
        }
        __syncthreads();

#pragma unroll 1
        for (int kk = 0; kk < 8; kk++) {
            const int k0 = kk * 16;
            uint32_t ah[2][4], al[2][4];
#pragma unroll
            for (int i = 0; i < 2; i++) {
                int r0 = wm + i * 16 + g;
                int r1 = r0 + 8;
                ah[i][0] = *(const uint32_t*)(sm + SMEM_A_HI + (r0 * LDS + k0 + 2 * t4) * 2);
                ah[i][1] = *(const uint32_t*)(sm + SMEM_A_HI + (r1 * LDS + k0 + 2 * t4) * 2);
                ah[i][2] = *(const uint32_t*)(sm + SMEM_A_HI + (r0 * LDS + k0 + 8 + 2 * t4) * 2);
                ah[i][3] = *(const uint32_t*)(sm + SMEM_A_HI + (r1 * LDS + k0 + 8 + 2 * t4) * 2);
            }
            // pass 0: A_hi x B_hi
#pragma unroll
            for (int j = 0; j < 8; j++) {
                int n = wn + j * 8 + g;
                uint32_t b0 = *(const uint32_t*)(sm + SMEM_B_HI + (n * LDS + k0 + 2 * t4) * 2);
                uint32_t b1 = *(const uint32_t*)(sm + SMEM_B_HI + (n * LDS + k0 + 8 + 2 * t4) * 2);
                mma16816(acc[0][j], ah[0], b0, b1);
                mma16816(acc[1][j], ah[1], b0, b1);
            }
            // pass 1: A_hi x B_lo
#pragma unroll
            for (int j = 0; j < 8; j++) {
                int n = wn + j * 8 + g;
                uint32_t b0 = *(const uint32_t*)(sm + SMEM_B_LO + (n * LDS + k0 + 2 * t4) * 2);
                uint32_t b1 = *(const uint32_t*)(sm + SMEM_B_LO + (n * LDS + k0 + 8 + 2 * t4) * 2);
                mma16816(acc[0][j], ah[0], b0, b1);
                mma16816(acc[1][j], ah[1], b0, b1);
            }
            // pass 2: A_lo x B_hi
#pragma unroll
            for (int i = 0; i < 2; i++) {
                int r0 = wm + i * 16 + g;
                int r1 = r0 + 8;
                al[i][0] = *(const uint32_t*)(sm + SMEM_A_LO + (r0 * LDS + k0 + 2 * t4) * 2);
                al[i][1] = *(const uint32_t*)(sm + SMEM_A_LO + (r1 * LDS + k0 + 2 * t4) * 2);
                al[i][2] = *(const uint32_t*)(sm + SMEM_A_LO + (r0 * LDS + k0 + 8 + 2 * t4) * 2);
                al[i][3] = *(const uint32_t*)(sm + SMEM_A_LO + (r1 * LDS + k0 + 8 + 2 * t4) * 2);
            }
#pragma unroll
            for (int j = 0; j < 8; j++) {
                int n = wn + j * 8 + g;
                uint32_t b0 = *(const uint32_t*)(sm + SMEM_B_HI + (n * LDS + k0 + 2 * t4) * 2);
                uint32_t b1 = *(const uint32_t*)(sm + SMEM_B_HI + (n * LDS + k0 + 8 + 2 * t4) * 2);
                mma16816(acc[0][j], al[0], b0, b1);
                mma16816(acc[1][j], al[1], b0, b1);
            }
        }
        __syncthreads();
    }

    // epilogue: thread owns rows (g, g+8) per m-frag, cols 2t,2t+1 per n-frag
    const int col0 = proj_mode ? (int)blockIdx.y * 128 : 0;
    const bool useb = bias && (!proj_mode || blockIdx.y == 1);
#pragma unroll
    for (int i = 0; i < 2; i++) {
        int r0 = m0 + wm + i * 16 + g;
        int r1 = r0 + 8;
#pragma unroll
        for (int j = 0; j < 8; j++) {
            int c = wn + j * 8 + 2 * t4;
            float b0v = 0.f, b1v = 0.f;
            if (useb) { b0v = bias[c]; b1v = bias[c + 1]; }
            if (r0 < M)
                *(float2*)(out + (size_t)r0 * out_stride + col0 + c) =
                    make_float2(acc[i][j][0] + b0v, acc[i][j][1] + b1v);
            if (r1 < M)
                *(float2*)(out + (size_t)r1 * out_stride + col0 + c) =
                    make_float2(acc[i][j][2] + b0v, acc[i][j][3] + b1v);
        }
    }
}

// ============================================================
// CSR build: zero -> histogram -> 3-phase parallel scan -> scatter
// ============================================================
__global__ void zero_counts(int n) {
    int i = blockIdx.x * blockDim.x + threadIdx.x;
    if (i < n) g_count[i] = 0;
}

__global__ void hist_kernel(const int* __restrict__ dists, int E) {
    int e = blockIdx.x * blockDim.x + threadIdx.x;
    if (e < E) atomicAdd(&g_count[dists[e]], 1);
}

#define SCAN_BLK 256
#define SCAN_CHUNK 1024

__global__ void scan_reduce(int M) {
    __shared__ int sdata[SCAN_BLK];
    int base = blockIdx.x * SCAN_CHUNK;
    int t = threadIdx.x;
    int s = 0;
#pragma unroll
    for (int i = 0; i < 4; i++) {
        int idx = base + t + i * SCAN_BLK;
        if (idx < M) s += g_count[idx];
    }
    sdata[t] = s;
    __syncthreads();
    for (int off = 128; off > 0; off >>= 1) {
        if (t < off) sdata[t] += sdata[t + off];
        __syncthreads();
    }
    if (t == 0) g_bsum[blockIdx.x] = sdata[0];
}

__global__ void scan_partials(int nblk) {
    __shared__ int sh[64];
    int t = threadIdx.x;
    int v = (t < nblk) ? g_bsum[t] : 0;
    sh[t] = v;
    __syncthreads();
    for (int off = 1; off < 64; off <<= 1) {
        int u = (t >= off) ? sh[t - off] : 0;
        __syncthreads();
        sh[t] += u;
        __syncthreads();
    }
    if (t < nblk) g_boff[t] = (t == 0) ? 0 : sh[t - 1];
}

__global__ void scan_final(int M) {
    __shared__ int warpsums[SCAN_BLK / 32];
    int base = blockIdx.x * SCAN_CHUNK;
    int t = threadIdx.x;
    int lane = t & 31, wid = t >> 5;

    int idx0 = base + t * 4;
    int c[4];
#pragma unroll
    for (int i = 0; i < 4; i++) c[i] = (idx0 + i < M) ? g_count[idx0 + i] : 0;
    int tsum = c[0] + c[1] + c[2] + c[3];

    int v = tsum;
#pragma unroll
    for (int off = 1; off < 32; off <<= 1) {
        int u = __shfl_up_sync(0xffffffff, v, off);
        if (lane >= off) v += u;
    }
    if (lane == 31) warpsums[wid] = v;
    __syncthreads();
    if (wid == 0) {
        int wv = (lane < SCAN_BLK / 32) ? warpsums[lane] : 0;
#pragma unroll
        for (int off = 1; off < 8; off <<= 1) {
            int u = __shfl_up_sync(0xffffffff, wv, off);
            if (lane >= off) wv += u;
        }
        if (lane < SCAN_BLK / 32) warpsums[lane] = wv;
    }
    __syncthreads();

    int excl = v - tsum + (wid ? warpsums[wid - 1] : 0) + g_boff[blockIdx.x];
    int run = excl;
#pragma unroll
    for (int i = 0; i < 4; i++) {
        int idx = idx0 + i;
        if (idx < M) {
            g_off[idx] = run;
            g_cur[idx] = run;
            run += c[i];
            if (idx == M - 1) g_off[M] = run;
        }
    }
}

__global__ void scatter_kernel(const int* __restrict__ sources,
                               const int* __restrict__ dists,
                               const float* __restrict__ weights, int E) {
    int e = blockIdx.x * blockDim.x + threadIdx.x;
    if (e >= E) return;
    int d = dists[e];
    int p = atomicAdd(&g_cur[d], 1);
    g_edge[p] = make_int2(sources[e], __float_as_int(weights[e]));
}

// ============================================================
// Aggregation: one warp per node.
// agg[d] = (deg>0) ? P2b[d] + max_e( P1[src_e] + w_e * w_row ) : 0
// ============================================================
__global__ void agg_kernel(const float* __restrict__ Wm, int M) {
    int warp = (blockIdx.x * blockDim.x + threadIdx.x) >> 5;
    int lane = threadIdx.x & 31;
    if (warp >= M) return;

    int beg = g_off[warp];
    int end = g_off[warp + 1];

    const float4 wr = *(const float4*)(Wm + (size_t)256 * HID + lane * 4);

    const float NINF = __int_as_float(0xff800000);
    float4 acc = make_float4(NINF, NINF, NINF, NINF);

#pragma unroll 2
    for (int i = beg; i < end; i++) {
        int2  e = g_edge[i];
        float w = __int_as_float(e.y);
        const float4 p = *(const float4*)(g_P + (size_t)e.x * (2 * HID) + lane * 4);
        acc.x = fmaxf(acc.x, fmaf(w, wr.x, p.x));
        acc.y = fmaxf(acc.y, fmaf(w, wr.y, p.y));
        acc.z = fmaxf(acc.z, fmaf(w, wr.z, p.z));
        acc.w = fmaxf(acc.w, fmaf(w, wr.w, p.w));
    }

    float4 o;
    if (end > beg) {
        const float4 q = *(const float4*)(g_P + (size_t)warp * (2 * HID) + HID + lane * 4);
        o = make_float4(q.x + acc.x, q.y + acc.y, q.z + acc.z, q.w + acc.w);
    } else {
        o = make_float4(0.f, 0.f, 0.f, 0.f);
    }
    *(float4*)(g_agg + (size_t)warp * HID + lane * 4) = o;
}

// ============================================================
extern "C" void kernel_launch(void* const* d_in, const int* in_sizes, int n_in,
                              void* d_out, int out_size) {
    const float* z   = (const float*)d_in[0];
    const int*   src = (const int*)d_in[1];
    const int*   dst = (const int*)d_in[2];
    const float* w   = (const float*)d_in[3];
    const float* Wm  = (const float*)d_in[4];
    const float* bm  = (const float*)d_in[5];
    const float* Wu  = (const float*)d_in[6];
    const float* bu  = (const float*)d_in[7];
    float* out = (float*)d_out;

    int M = in_sizes[0] / HID;   // nodes
    int E = in_sizes[1];         // edges

    int nbm = (M + 127) / 128;
    int nchunk = (M + SCAN_CHUNK - 1) / SCAN_CHUNK;

    static cudaStream_t s2 = nullptr;
    static cudaEvent_t evFork = nullptr, evJoin = nullptr;
    if (!s2) {
        cudaFuncSetAttribute(mma_gemm, cudaFuncAttributeMaxDynamicSharedMemorySize, SMEM_SZ);
        cudaStreamCreateWithFlags(&s2, cudaStreamNonBlocking);
        cudaEventCreateWithFlags(&evFork, cudaEventDisableTiming);
        cudaEventCreateWithFlags(&evJoin, cudaEventDisableTiming);
    }

    // fork: CSR build on s2, independent of the proj GEMM chain on stream 0
    cudaEventRecord(evFork, 0);
    cudaStreamWaitEvent(s2, evFork, 0);

    // stream 0: weight prep + projection GEMM (writes g_P)
    prep_w<<<128, 256>>>(Wm, Wu);
    mma_gemm<<<dim3(nbm, 2), 256, SMEM_SZ>>>(z, 0, bm, nullptr, 1, 2 * HID, 1, 1, M);

    // stream s2: CSR build (counts -> offsets -> packed edge scatter)
    zero_counts<<<(M + 255) / 256, 256, 0, s2>>>(M);
    hist_kernel<<<(E + 255) / 256, 256, 0, s2>>>(dst, E);
    scan_reduce<<<nchunk, SCAN_BLK, 0, s2>>>(M);
    scan_partials<<<1, 64, 0, s2>>>(nchunk);
    scan_final<<<nchunk, SCAN_BLK, 0, s2>>>(M);
    scatter_kernel<<<(E + 255) / 256, 256, 0, s2>>>(src, dst, w, E);

    // join: agg needs both g_P (stream 0) and the CSR (s2)
    cudaEventRecord(evJoin, s2);
    cudaStreamWaitEvent(0, evJoin, 0);

    {
        long long threads = (long long)M * 32;
        int blocks = (int)((threads + 255) / 256);
        agg_kernel<<<blocks, 256>>>(Wm, M);
    }
    // upd: out = [z | agg] @ Wu + bu, B tiles 2/3 (K-tile 1 reads g_agg device-side)
    mma_gemm<<<nbm, 256, SMEM_SZ>>>(z, 2, bu, out, 0, HID, 0, 2, M);
}